// round 12
// baseline (speedup 1.0000x reference)
#include <cuda_runtime.h>
#include <cuda_bf16.h>
#include <cstdint>
#include <math.h>

// VectorQuantizer: N=262144 rows, D=256, K=1024 codes.
// out = [quantized_st (67108864 f32), loss, perplexity]
//
// bf16 mma.sync (HMMA fallback, baseline PTX) filter -> conservative per-row
// candidate sets -> bit-exact rescore with the validated XLA:CPU arithmetic
// (chained fp32 fma k-ascending; d = fl(fl(a+b)-fl(2c)); lowest-index ties;
// out = fl(x + fl(q-x))).

#define NROWS   262144
#define DIM     256
#define NCODES  1024
#define BM      128
#define QELEMS  67108864
#define CAP     32

#define NTHRF   256
#define NWARP   8
#define CHUNK   64
#define NCH     (NCODES / CHUNK)   // 16
#define XSTR    264                 // bf16 elems per padded row (conflict-free)
#define ESTR    264

__device__ float          g_bsq[NCODES];
__device__ int            g_counts[NCODES];
__device__ double         g_sqsum;
__device__ __nv_bfloat16  g_cbbf[NCODES * DIM];
__device__ int            g_cnt[NROWS];
__device__ int            g_cand[(size_t)NROWS * CAP];

// ------------------------- helpers -------------------------
static __device__ __forceinline__ unsigned int okey(float s) {
    unsigned int b = __float_as_uint(s);
    return (b & 0x80000000u) ? ~b : (b | 0x80000000u);
}
static __device__ __forceinline__ unsigned long long umin64(unsigned long long a,
                                                            unsigned long long b) {
    return a < b ? a : b;
}
static __device__ __forceinline__ void mma16816(float* d, uint32_t a0, uint32_t a1,
                                                uint32_t a2, uint32_t a3,
                                                uint32_t b0, uint32_t b1) {
    asm volatile(
        "mma.sync.aligned.m16n8k16.row.col.f32.bf16.bf16.f32 "
        "{%0,%1,%2,%3}, {%4,%5,%6,%7}, {%8,%9}, {%0,%1,%2,%3};"
        : "+f"(d[0]), "+f"(d[1]), "+f"(d[2]), "+f"(d[3])
        : "r"(a0), "r"(a1), "r"(a2), "r"(a3), "r"(b0), "r"(b1));
}

// ---------------- init: exact b_k chains + bf16 codebook ----------------
__global__ void vq_init_kernel(const float* __restrict__ cb) {
    __shared__ float row[DIM];
    int k = blockIdx.x;
    int t = threadIdx.x;                 // 256 threads
    if (t < 64) {
        float4 v = ((const float4*)(cb + (size_t)k * DIM))[t];
        row[t * 4 + 0] = v.x; row[t * 4 + 1] = v.y;
        row[t * 4 + 2] = v.z; row[t * 4 + 3] = v.w;
    }
    g_cbbf[(size_t)k * DIM + t] = __float2bfloat16(cb[(size_t)k * DIM + t]);
    __syncthreads();
    if (t == 0) {
        float s = 0.f;
        #pragma unroll 8
        for (int j = 0; j < DIM; ++j) {
            float w = row[j];
            s = __fadd_rn(s, __fmul_rn(w, w));   // strict sequential, j ascending
        }
        g_bsq[k] = s;
        g_counts[k] = 0;
        if (k == 0) g_sqsum = 0.0;
    }
}

// ---------------- filter: mma.sync bf16 scores -> candidate sets ----------------
// smem layout (bytes):
//   xsm  : 128 rows * XSTR bf16            = 67584
//   esm  : 2 buf * 64 rows * ESTR bf16     = 67584
//   seps : 128 f32                          = 512
//   scnt : 128 int                          = 512
//   scand: 128 * CAP int                    = 16384
#define XS_OFF   0
#define ES_OFF   67584
#define EPS_OFF  (ES_OFF + 67584)
#define CNT_OFF  (EPS_OFF + 512)
#define CAND_OFF (CNT_OFF + 512)
#define SMEMF    (CAND_OFF + 16384)

__global__ __launch_bounds__(NTHRF, 1)
void vq_filter_kernel(const float* __restrict__ x) {
    extern __shared__ char smem[];
    __nv_bfloat16* xsm = (__nv_bfloat16*)(smem + XS_OFF);
    __nv_bfloat16* esm = (__nv_bfloat16*)(smem + ES_OFF);
    float* seps = (float*)(smem + EPS_OFF);
    int*   scnt = (int*)(smem + CNT_OFF);
    int*   scand = (int*)(smem + CAND_OFF);

    const int tid  = threadIdx.x;
    const int lane = tid & 31;
    const int w    = tid >> 5;           // 0..7
    const int g    = lane >> 2;          // 0..7
    const int q    = lane & 3;           // 0..3
    const int m0 = blockIdx.x * BM;
    const float* xg = x + (size_t)m0 * DIM;

    if (tid < 128) scnt[tid] = 0;

    // stage x -> bf16 padded tile (8192 float4 segs; 32 per thread)
    #pragma unroll
    for (int i = 0; i < 32; ++i) {
        int idx = i * NTHRF + tid;
        int row = idx >> 6, seg = idx & 63;
        float4 v = *(const float4*)(xg + (size_t)row * DIM + seg * 4);
        uint32_t u0, u1;
        asm("cvt.rn.satfinite.bf16x2.f32 %0, %1, %2;" : "=r"(u0) : "f"(v.y), "f"(v.x));
        asm("cvt.rn.satfinite.bf16x2.f32 %0, %1, %2;" : "=r"(u1) : "f"(v.w), "f"(v.z));
        *(uint2*)(xsm + row * XSTR + seg * 4) = make_uint2(u0, u1);
    }

    // per-row eps from ||x||
    if (tid < 128) {
        float axr = 0.f;
        const float4* xr = (const float4*)(xg + (size_t)tid * DIM);
        #pragma unroll 8
        for (int j = 0; j < 64; ++j) {
            float4 v = xr[j];
            axr += v.x * v.x + v.y * v.y + v.z * v.z + v.w * v.w;
        }
        seps[tid] = 2e-4f + 4e-4f * sqrtf(axr);
    }

    // stage codebook chunk 0 into buffer 0
    #pragma unroll
    for (int i = 0; i < 8; ++i) {
        int idx = i * NTHRF + tid;       // 2048 uint4 segs
        int r = idx >> 5, s = idx & 31;
        uint4 v = *(const uint4*)(&g_cbbf[(size_t)r * DIM + s * 8]);
        *(uint4*)(esm + r * ESTR + s * 8) = v;
    }
    __syncthreads();

    const int xrow0 = w * 16 + g;
    const float eps0 = seps[xrow0];
    const float eps1 = seps[xrow0 + 8];
    float rmin0 = 3.4e38f, rmin1 = 3.4e38f;

    uint4 pf[8];
    for (int ch = 0; ch < NCH; ++ch) {
        const int buf = ch & 1;
        const int cb0 = ch * CHUNK;
        const __nv_bfloat16* eb = esm + buf * (64 * ESTR);

        // prefetch next chunk
        if (ch + 1 < NCH) {
            #pragma unroll
            for (int i = 0; i < 8; ++i) {
                int idx = i * NTHRF + tid;
                int r = idx >> 5, s = idx & 31;
                pf[i] = *(const uint4*)(&g_cbbf[(size_t)((ch + 1) * CHUNK + r) * DIM + s * 8]);
            }
        }

        float acc[8][4];
        #pragma unroll
        for (int t = 0; t < 8; ++t) {
            acc[t][0] = 0.f; acc[t][1] = 0.f; acc[t][2] = 0.f; acc[t][3] = 0.f;
        }

        #pragma unroll 4
        for (int kk = 0; kk < 16; ++kk) {
            const int kb = kk * 16 + q * 2;
            uint32_t a0 = *(const uint32_t*)(xsm + (size_t)xrow0 * XSTR + kb);
            uint32_t a1 = *(const uint32_t*)(xsm + (size_t)(xrow0 + 8) * XSTR + kb);
            uint32_t a2 = *(const uint32_t*)(xsm + (size_t)xrow0 * XSTR + kb + 8);
            uint32_t a3 = *(const uint32_t*)(xsm + (size_t)(xrow0 + 8) * XSTR + kb + 8);
            #pragma unroll
            for (int t = 0; t < 8; ++t) {
                const __nv_bfloat16* bp = eb + (size_t)(t * 8 + g) * ESTR + kb;
                uint32_t b0 = *(const uint32_t*)(bp);
                uint32_t b1 = *(const uint32_t*)(bp + 8);
                mma16816(acc[t], a0, a1, a2, a3, b0, b1);
            }
        }

        // scores + running min + online candidate selection
        float m0l = 3.4e38f, m1l = 3.4e38f;
        float sc[8][4];
        #pragma unroll
        for (int t = 0; t < 8; ++t) {
            int c0 = cb0 + t * 8 + q * 2;
            float b20 = __ldg(&g_bsq[c0]);
            float b21 = __ldg(&g_bsq[c0 + 1]);
            sc[t][0] = b20 - 2.0f * acc[t][0];
            sc[t][1] = b21 - 2.0f * acc[t][1];
            sc[t][2] = b20 - 2.0f * acc[t][2];
            sc[t][3] = b21 - 2.0f * acc[t][3];
            m0l = fminf(m0l, fminf(sc[t][0], sc[t][1]));
            m1l = fminf(m1l, fminf(sc[t][2], sc[t][3]));
        }
        m0l = fminf(m0l, __shfl_xor_sync(0xFFFFFFFFu, m0l, 1));
        m0l = fminf(m0l, __shfl_xor_sync(0xFFFFFFFFu, m0l, 2));
        m1l = fminf(m1l, __shfl_xor_sync(0xFFFFFFFFu, m1l, 1));
        m1l = fminf(m1l, __shfl_xor_sync(0xFFFFFFFFu, m1l, 2));
        rmin0 = fminf(rmin0, m0l);
        rmin1 = fminf(rmin1, m1l);
        const float thr0 = rmin0 + eps0;
        const float thr1 = rmin1 + eps1;
        #pragma unroll
        for (int t = 0; t < 8; ++t) {
            int c0 = cb0 + t * 8 + q * 2;
            if (sc[t][0] <= thr0) {
                int s = atomicAdd(&scnt[xrow0], 1);
                if (s < CAP) scand[xrow0 * CAP + s] = c0;
            }
            if (sc[t][1] <= thr0) {
                int s = atomicAdd(&scnt[xrow0], 1);
                if (s < CAP) scand[xrow0 * CAP + s] = c0 + 1;
            }
            if (sc[t][2] <= thr1) {
                int s = atomicAdd(&scnt[xrow0 + 8], 1);
                if (s < CAP) scand[(xrow0 + 8) * CAP + s] = c0;
            }
            if (sc[t][3] <= thr1) {
                int s = atomicAdd(&scnt[xrow0 + 8], 1);
                if (s < CAP) scand[(xrow0 + 8) * CAP + s] = c0 + 1;
            }
        }

        // publish next chunk into the idle buffer
        if (ch + 1 < NCH) {
            __nv_bfloat16* dst = esm + (buf ^ 1) * (64 * ESTR);
            #pragma unroll
            for (int i = 0; i < 8; ++i) {
                int idx = i * NTHRF + tid;
                int r = idx >> 5, s = idx & 31;
                *(uint4*)(dst + r * ESTR + s * 8) = pf[i];
            }
            __syncthreads();
        }
    }

    __syncthreads();
    if (tid < 128) {
        int c = scnt[tid];
        g_cnt[m0 + tid] = c;
        int cc = c < CAP ? c : CAP;
        for (int j = 0; j < cc; ++j)
            g_cand[(size_t)(m0 + tid) * CAP + j] = scand[tid * CAP + j];
    }
}

// ---------------- rescore: exact chains on candidates + fused output ----------------
#define XPAD 257
__global__ __launch_bounds__(128, 1)
void vq_rescore_kernel(const float* __restrict__ x, const float* __restrict__ cb,
                       float* __restrict__ out) {
    extern __shared__ char smemc[];
    float* xsm = (float*)smemc;                          // [128][257]
    int*   sidx = (int*)(smemc + BM * XPAD * 4);         // +512 B
    double* dred = (double*)(smemc + BM * XPAD * 4 + 512);

    const int tid = threadIdx.x;
    const int m0 = blockIdx.x * BM;
    const float* xg = x + (size_t)m0 * DIM;

    #pragma unroll
    for (int i = 0; i < 64; ++i) {
        int idx = i * 128 + tid;
        int row = idx >> 6, seg = idx & 63;
        float4 v = *(const float4*)(xg + (size_t)row * DIM + seg * 4);
        float* d = xsm + row * XPAD + seg * 4;
        d[0] = v.x; d[1] = v.y; d[2] = v.z; d[3] = v.w;
    }
    __syncthreads();

    // exact a chain (strict sequential, j ascending)
    const float* xr = xsm + tid * XPAD;
    float a = 0.f;
    #pragma unroll 8
    for (int j = 0; j < DIM; ++j) {
        float v = xr[j];
        a = __fadd_rn(a, __fmul_rn(v, v));
    }

    const int grow = m0 + tid;
    int cnt = g_cnt[grow];
    unsigned long long best = 0xFFFFFFFFFFFFFFFFULL;
    if (cnt >= 1 && cnt <= CAP) {
        for (int i = 0; i < cnt; ++i) {
            int k = g_cand[(size_t)grow * CAP + i];
            const float* er = cb + (size_t)k * DIM;
            float c = 0.f;
            #pragma unroll 8
            for (int j = 0; j < DIM; ++j)
                c = __fmaf_rn(xr[j], __ldg(er + j), c);   // chained fma, j ascending
            float d = __fsub_rn(__fadd_rn(a, g_bsq[k]), __fmul_rn(2.0f, c));
            best = umin64(best, ((unsigned long long)okey(d) << 32) | (unsigned)k);
        }
    } else {
        for (int k = 0; k < NCODES; ++k) {               // overflow fallback: exact scan
            const float* er = cb + (size_t)k * DIM;
            float c = 0.f;
            #pragma unroll 8
            for (int j = 0; j < DIM; ++j)
                c = __fmaf_rn(xr[j], __ldg(er + j), c);
            float d = __fsub_rn(__fadd_rn(a, g_bsq[k]), __fmul_rn(2.0f, c));
            best = umin64(best, ((unsigned long long)okey(d) << 32) | (unsigned)k);
        }
    }
    int idx = (int)(best & 0xFFFFFFFFULL);
    sidx[tid] = idx;
    atomicAdd(&g_counts[idx], 1);
    __syncthreads();

    // fused straight-through output + MSE (coalesced)
    double sq = 0.0;
    float* og = out + (size_t)m0 * DIM;
    for (int i = tid; i < BM * DIM; i += 128) {
        int row = i >> 8, col = i & 255;
        float e = cb[(size_t)sidx[row] * DIM + col];
        float xv = xsm[row * XPAD + col];
        float df = __fsub_rn(e, xv);                 // fl(q - x)
        og[i] = __fadd_rn(xv, df);                   // fl(x + fl(q - x))
        float s2 = __fmul_rn(df, df);
        sq += (double)s2;
    }
    dred[tid] = sq;
    __syncthreads();
    for (int s = 64; s > 0; s >>= 1) {
        if (tid < s) dred[tid] += dred[tid + s];
        __syncthreads();
    }
    if (tid == 0) atomicAdd(&g_sqsum, dred[0]);
}

// ---------------- finalize: loss + perplexity ----------------
__global__ void vq_final_kernel(float* __restrict__ out, long long out_size) {
    __shared__ float terms[NCODES];
    int t = threadIdx.x;
    float p = __fdiv_rn((float)g_counts[t], (float)NROWS);
    terms[t] = __fmul_rn(p, logf(__fadd_rn(p, 1e-10f)));
    __syncthreads();
    if (t == 0 && out_size >= (long long)QELEMS + 2) {
        float s = 0.f;
        for (int k = 0; k < NCODES; ++k) s = __fadd_rn(s, terms[k]);
        float m = (float)(g_sqsum / (double)QELEMS);
        out[QELEMS]     = __fadd_rn(m, __fmul_rn(0.25f, m));
        out[QELEMS + 1] = expf(-s);
    }
}

extern "C" void kernel_launch(void* const* d_in, const int* in_sizes, int n_in,
                              void* d_out, int out_size) {
    const float* x  = (const float*)d_in[0];   // inputs  [8,32,32,32,256]
    const float* cb = (const float*)d_in[1];   // codebook [1024,256]
    float* out = (float*)d_out;

    cudaFuncSetAttribute(vq_filter_kernel,
                         cudaFuncAttributeMaxDynamicSharedMemorySize, SMEMF);
    const int smemc = BM * XPAD * 4 + 512 + BM * 8;
    cudaFuncSetAttribute(vq_rescore_kernel,
                         cudaFuncAttributeMaxDynamicSharedMemorySize, smemc);

    vq_init_kernel<<<NCODES, 256>>>(cb);
    vq_filter_kernel<<<NROWS / BM, NTHRF, SMEMF>>>(x);
    vq_rescore_kernel<<<NROWS / BM, 128, smemc>>>(x, cb, out);
    vq_final_kernel<<<1, NCODES>>>(out, (long long)out_size);
}